// round 5
// baseline (speedup 1.0000x reference)
#include <cuda_runtime.h>
#include <math.h>
#include <stdint.h>

#define NDET 512
#define NC   81
#define HW   784
#define NMS_THRESH 0.5
#define EPSV 1e-4
#define TAU  6e-6          // flag margin (iou units); worst-case f32 err ~1.3e-6
#define FLAG_CAP (1 << 16)
#define NTILE 36           // upper-triangular 8x8 tile count

// ---------------- scratch (static device memory) ----------------------------
__device__ __align__(16) float  g_Pf[2][NDET][HW];          // sorted probs (f32)
__device__ double        g_ud[2][NDET];                     // sorted row sums (f64)
__device__ __align__(16) float g_partial[2][2][NDET][NDET]; // [side][khalf] partials
__device__ __align__(16) unsigned int g_bits[2][NDET][16];  // packed mask rows
__device__ int           g_order[NDET];
__device__ int           g_ticket[2 * NTILE];
__device__ int           g_nflag;
__device__ int           g_flags[FLAG_CAP];                 // (side<<20)|(i<<10)|j

// ---------------- 1. sigmoid-gather + inline rank + row sums ----------------
// grid 1024 x 256 thr: block b = (side, n). Rank computed inline (O(N) L2-hot).
__global__ void prob_kernel(const float* __restrict__ left,
                            const float* __restrict__ right,
                            const float* __restrict__ scores,
                            const int*   __restrict__ labels,
                            float*       __restrict__ out) {
    int b = blockIdx.x;
    int side = b >> 9;
    int n = b & (NDET - 1);
    int tid = threadIdx.x;

    if (b == 0) {   // reset cross-kernel state (completes before gemm launch)
        if (tid < 2 * NTILE) g_ticket[tid] = 0;
        if (tid == 2 * NTILE) g_nflag = 0;
    }

    // rank of n under argsort(-scores), stable
    __shared__ int s_cnt;
    if (tid == 0) s_cnt = 0;
    __syncthreads();
    float sn = __ldg(&scores[n]);
    int c = 0;
    for (int j = tid; j < NDET; j += 256) {
        float sj = __ldg(&scores[j]);
        c += (sj > sn) || (sj == sn && j < n);
    }
    for (int o = 16; o; o >>= 1) c += __shfl_down_sync(0xffffffffu, c, o);
    if ((tid & 31) == 0) atomicAdd(&s_cnt, c);
    __syncthreads();
    int r = s_cnt;
    if (side == 0 && tid == 0) g_order[r] = n;

    const float* base = side ? right : left;
    int cls = labels[n];
    const float* row = base + ((size_t)n * NC + cls) * HW;
    float* orow = out + ((size_t)side * NDET + n) * HW;
    float* prow = g_Pf[side][r];

    double s = 0.0;
    for (int k = tid; k < HW; k += 256) {
        float x = row[k];
        float p = 1.0f / (1.0f + expf(-x));
        orow[k] = p;
        prow[k] = p;
        s += (double)p;
    }
    __shared__ double red[8];
    for (int o = 16; o; o >>= 1) s += __shfl_down_sync(0xffffffffu, s, o);
    if ((tid & 31) == 0) red[tid >> 5] = s;
    __syncthreads();
    if (tid == 0) {
        double tt = 0.0;
#pragma unroll
        for (int w = 0; w < 8; ++w) tt += red[w];
        g_ud[side][r] = tt;
    }
}

// ---------------- 2. f32 Gram partials + fused f64 combine/threshold --------
// grid 144 = 36 upper-tri tiles x {khalf,side}. Second-finisher block per tile
// combines both K-halves in f64, packs bits, emits near-threshold flags.
__global__ void __launch_bounds__(256) gemm_fused_kernel() {
    int t = blockIdx.x % NTILE;
    int z = blockIdx.x / NTILE;       // 0..3
    int khalf = z & 1, side = z >> 1;
    int by = 0, rem = t;
    while (rem >= 8 - by) { rem -= 8 - by; ++by; }
    int bx = by + rem;                // bx >= by
    int arow0 = by * 64, brow0 = bx * 64;
    int kbeg = khalf ? 400 : 0;
    int kend = khalf ? HW : 400;

    __shared__ __align__(16) float As[16][68];
    __shared__ __align__(16) float Bs[16][68];
    int tid = threadIdx.x;
    int tx = tid & 15, ty = tid >> 4;
    const float* P = &g_Pf[side][0][0];

    float s[4][4];
#pragma unroll
    for (int m = 0; m < 4; ++m)
#pragma unroll
        for (int n = 0; n < 4; ++n) s[m][n] = 0.0f;

    int rr = tid >> 2, kq = (tid & 3) * 4;
    for (int kt = kbeg; kt < kend; kt += 16) {
        float4 av = *(const float4*)&P[(size_t)(arow0 + rr) * HW + kt + kq];
        float4 bv = *(const float4*)&P[(size_t)(brow0 + rr) * HW + kt + kq];
        As[kq + 0][rr] = av.x; As[kq + 1][rr] = av.y;
        As[kq + 2][rr] = av.z; As[kq + 3][rr] = av.w;
        Bs[kq + 0][rr] = bv.x; Bs[kq + 1][rr] = bv.y;
        Bs[kq + 2][rr] = bv.z; Bs[kq + 3][rr] = bv.w;
        __syncthreads();
        float tacc[4][4];
#pragma unroll
        for (int m = 0; m < 4; ++m)
#pragma unroll
            for (int n = 0; n < 4; ++n) tacc[m][n] = 0.0f;
#pragma unroll
        for (int kk = 0; kk < 16; ++kk) {
            float4 a4 = *(const float4*)&As[kk][ty * 4];
            float4 b4 = *(const float4*)&Bs[kk][tx * 4];
            float a[4] = {a4.x, a4.y, a4.z, a4.w};
            float bb[4] = {b4.x, b4.y, b4.z, b4.w};
#pragma unroll
            for (int m = 0; m < 4; ++m)
#pragma unroll
                for (int n = 0; n < 4; ++n) tacc[m][n] = fmaf(a[m], bb[n], tacc[m][n]);
        }
#pragma unroll
        for (int m = 0; m < 4; ++m)
#pragma unroll
            for (int n = 0; n < 4; ++n) s[m][n] = __fadd_rn(s[m][n], tacc[m][n]);
        __syncthreads();
    }

    // write this half's partial
    float* dst = &g_partial[side][khalf][0][0];
#pragma unroll
    for (int m = 0; m < 4; ++m) {
        int gi = arow0 + ty * 4 + m;
        float4 v = make_float4(s[m][0], s[m][1], s[m][2], s[m][3]);
        *(float4*)&dst[(size_t)gi * NDET + brow0 + tx * 4] = v;
    }
    __threadfence();
    __syncthreads();
    __shared__ int s_old;
    if (tid == 0) s_old = atomicAdd(&g_ticket[side * NTILE + t], 1);
    __syncthreads();
    if (s_old != 1) return;

    // second finisher: combine halves (f64), threshold, pack bits, flag
    __threadfence();
    if (tid < 128) {
        int r = tid >> 1, half = tid & 1;
        int gi = arow0 + r;
        double den = g_ud[side][gi] + EPSV;
        int j0 = brow0 + half * 32;
        const float* q0 = &g_partial[side][0][gi][j0];
        const float* q1 = &g_partial[side][1][gi][j0];
        unsigned int w = 0;
#pragma unroll 8
        for (int bbit = 0; bbit < 32; ++bbit) {
            double inter = (double)__ldcg(&q0[bbit]) + (double)__ldcg(&q1[bbit]);
            double mg = inter - 0.5 * den;
            if (mg >= 0.0) w |= (1u << bbit);
            int gj = j0 + bbit;
            if (gj > gi && fabs(mg) <= TAU * den) {
                int idx = atomicAdd(&g_nflag, 1);
                if (idx < FLAG_CAP)
                    g_flags[idx] = (side << 20) | (gi << 10) | gj;
            }
        }
        g_bits[side][gi][(brow0 >> 5) + half] = w;
    }
}

// ---------------- 3. post: refine (f64 exact) + skip-NMS + finalize ---------
// single block, 512 threads
__global__ void post_kernel(float* __restrict__ out, int out_size) {
    int tid = threadIdx.x;
    int lane = tid & 31;
    int warp = tid >> 5;
    __shared__ unsigned int s_sup[2][16];

    // 3a. exact f64 refinement of near-threshold pairs (16 warps)
    int nf = g_nflag;
    if (nf > FLAG_CAP) nf = FLAG_CAP;
    for (int p = warp; p < nf; p += 16) {
        int v = g_flags[p];
        int side = v >> 20, i = (v >> 10) & 1023, j = v & 1023;
        const float* Pi = g_Pf[side][i];
        const float* Pj = g_Pf[side][j];
        double sum = 0.0;
#pragma unroll
        for (int q = 0; q < 25; ++q) {
            int k = lane + q * 32;
            float a = (k < HW) ? Pi[k] : 0.0f;
            float b = (k < HW) ? Pj[k] : 0.0f;
            sum = fma((double)a, (double)b, sum);
        }
        for (int o = 16; o; o >>= 1) sum += __shfl_down_sync(0xffffffffu, sum, o);
        if (lane == 0) {
            double den = g_ud[side][i] + EPSV;
            unsigned int bit = 1u << (j & 31);
            unsigned int* w = &g_bits[side][i][j >> 5];
            if (sum / den >= NMS_THRESH) atomicOr(w, bit);
            else                         atomicAnd(w, ~bit);
        }
    }
    __syncthreads();

    // 3b. greedy skip-NMS: warp 0 -> side 0, warp 1 -> side 1 (parallel)
    if (warp < 2) {
        int side = warp;
        unsigned int removed = 0;   // lane w<16 holds suppression word w
        int i = 0;                  // top-ranked row always kept
        while (true) {
            int rw = i >> 5, rbit = i & 31;
            unsigned int hi = (rbit == 31) ? 0u : (0xFFFFFFFFu << (rbit + 1));
            unsigned int m = (lane < 16) ? __ldcg(&g_bits[side][i][lane]) : 0u;
            if (lane < rw) m = 0u;
            else if (lane == rw) m &= hi;
            removed |= m;
            unsigned int cand = (lane < 16) ? ~removed : 0u;
            if (lane < rw) cand = 0u;
            else if (lane == rw) cand &= hi;
            unsigned int ball = __ballot_sync(0xffffffffu, cand != 0u);
            if (!ball) break;
            int w = __ffs(ball) - 1;
            unsigned int word = __shfl_sync(0xffffffffu, cand, w);
            i = w * 32 + __ffs(word) - 1;
        }
        if (lane < 16) s_sup[side][lane] = removed;
    }
    __syncthreads();

    // 3c. finalize: keep[order[r]] = valid & !supL & !supR
    int r = tid;
    int n = g_order[r];
    bool valid = (g_ud[0][r] > 0.0) && (g_ud[1][r] > 0.0);
    bool supL = (s_sup[0][r >> 5] >> (r & 31)) & 1u;
    bool supR = (s_sup[1][r >> 5] >> (r & 31)) & 1u;
    float k = (valid && !supL && !supR) ? 1.0f : 0.0f;
    if (out_size >= 2 * NDET * HW + NDET)
        out[2 * NDET * HW + n] = k;
}

// ---------------- launch -----------------------------------------------------
extern "C" void kernel_launch(void* const* d_in, const int* in_sizes, int n_in,
                              void* d_out, int out_size) {
    const float* left   = (const float*)d_in[0];
    const float* right  = (const float*)d_in[1];
    const float* scores = (const float*)d_in[2];
    const int*   labels = (const int*)d_in[3];
    float* out = (float*)d_out;
    (void)in_sizes; (void)n_in;

    prob_kernel<<<2 * NDET, 256>>>(left, right, scores, labels, out);
    gemm_fused_kernel<<<4 * NTILE, 256>>>();
    post_kernel<<<1, NDET>>>(out, out_size);
}

// round 6
// speedup vs baseline: 2.0574x; 2.0574x over previous
#include <cuda_runtime.h>
#include <math.h>
#include <stdint.h>

#define NDET 512
#define NC   81
#define HW   784
#define NMS_THRESH 0.5
#define EPSV 1e-4
#define TAU  6e-6          // flag margin (iou units); worst-case f32 err ~1.2e-6
#define FLAG_CAP (1 << 16)

// ---------------- scratch (static device memory) ----------------------------
__device__ __align__(16) float  g_Pf[2][NDET][HW];          // sorted probs (f32)
__device__ double        g_ud[2][NDET];                     // sorted row sums (f64)
__device__ __align__(16) float g_partial[2][2][NDET][NDET]; // [side][khalf] partials
__device__ __align__(16) unsigned int g_bits[2][NDET][16];  // packed mask rows
__device__ int           g_order[NDET];
__device__ int           g_nflag;
__device__ int           g_flags[FLAG_CAP];                 // (side<<20)|(i<<10)|j

// ---------------- 1. sigmoid-gather + inline rank + row sums ----------------
__global__ void prob_kernel(const float* __restrict__ left,
                            const float* __restrict__ right,
                            const float* __restrict__ scores,
                            const int*   __restrict__ labels,
                            float*       __restrict__ out) {
    int b = blockIdx.x;
    int side = b >> 9;
    int n = b & (NDET - 1);
    int tid = threadIdx.x;

    if (b == 0 && tid == 0) g_nflag = 0;

    // rank of n under stable argsort(-scores)
    __shared__ int s_cnt;
    if (tid == 0) s_cnt = 0;
    __syncthreads();
    float sn = __ldg(&scores[n]);
    int c = 0;
    for (int j = tid; j < NDET; j += 256) {
        float sj = __ldg(&scores[j]);
        c += (sj > sn) || (sj == sn && j < n);
    }
    for (int o = 16; o; o >>= 1) c += __shfl_down_sync(0xffffffffu, c, o);
    if ((tid & 31) == 0) atomicAdd(&s_cnt, c);
    __syncthreads();
    int r = s_cnt;
    if (side == 0 && tid == 0) g_order[r] = n;

    const float* base = side ? right : left;
    int cls = labels[n];
    const float* row = base + ((size_t)n * NC + cls) * HW;
    float* orow = out + ((size_t)side * NDET + n) * HW;
    float* prow = g_Pf[side][r];

    double s = 0.0;
    for (int k = tid; k < HW; k += 256) {
        float x = row[k];
        float p = 1.0f / (1.0f + expf(-x));
        orow[k] = p;
        prow[k] = p;
        s += (double)p;
    }
    __shared__ double red[8];
    for (int o = 16; o; o >>= 1) s += __shfl_down_sync(0xffffffffu, s, o);
    if ((tid & 31) == 0) red[tid >> 5] = s;
    __syncthreads();
    if (tid == 0) {
        double tt = 0.0;
#pragma unroll
        for (int w = 0; w < 8; ++w) tt += red[w];
        g_ud[side][r] = tt;
    }
}

// ---------------- 2. f32 Gram partials (triangular, K-split 2) --------------
// grid (8,8,4): z = side*2 + khalf. BM=BN=64, BK=16, 4x4 micro-tile, all f32.
__global__ void __launch_bounds__(256) gemm_partial_kernel() {
    if (blockIdx.x < blockIdx.y) return;   // upper triangle tiles only
    int side  = blockIdx.z >> 1;
    int khalf = blockIdx.z & 1;
    int kbeg = khalf ? 400 : 0;
    int kend = khalf ? HW  : 400;

    __shared__ __align__(16) float As[16][68];
    __shared__ __align__(16) float Bs[16][68];
    int tid = threadIdx.x;
    int tx = tid & 15, ty = tid >> 4;
    int arow0 = blockIdx.y * 64;
    int brow0 = blockIdx.x * 64;
    const float* P = &g_Pf[side][0][0];

    float s[4][4];
#pragma unroll
    for (int m = 0; m < 4; ++m)
#pragma unroll
        for (int n = 0; n < 4; ++n) s[m][n] = 0.0f;

    int rr = tid >> 2, kq = (tid & 3) * 4;
    for (int kt = kbeg; kt < kend; kt += 16) {
        float4 av = *(const float4*)&P[(size_t)(arow0 + rr) * HW + kt + kq];
        float4 bv = *(const float4*)&P[(size_t)(brow0 + rr) * HW + kt + kq];
        As[kq + 0][rr] = av.x; As[kq + 1][rr] = av.y;
        As[kq + 2][rr] = av.z; As[kq + 3][rr] = av.w;
        Bs[kq + 0][rr] = bv.x; Bs[kq + 1][rr] = bv.y;
        Bs[kq + 2][rr] = bv.z; Bs[kq + 3][rr] = bv.w;
        __syncthreads();
        float tacc[4][4];
#pragma unroll
        for (int m = 0; m < 4; ++m)
#pragma unroll
            for (int n = 0; n < 4; ++n) tacc[m][n] = 0.0f;
#pragma unroll
        for (int kk = 0; kk < 16; ++kk) {
            float4 a4 = *(const float4*)&As[kk][ty * 4];
            float4 b4 = *(const float4*)&Bs[kk][tx * 4];
            float a[4] = {a4.x, a4.y, a4.z, a4.w};
            float bb[4] = {b4.x, b4.y, b4.z, b4.w};
#pragma unroll
            for (int m = 0; m < 4; ++m)
#pragma unroll
                for (int n = 0; n < 4; ++n) tacc[m][n] = fmaf(a[m], bb[n], tacc[m][n]);
        }
#pragma unroll
        for (int m = 0; m < 4; ++m)
#pragma unroll
            for (int n = 0; n < 4; ++n) s[m][n] = __fadd_rn(s[m][n], tacc[m][n]);
        __syncthreads();
    }

    float* dst = &g_partial[side][khalf][0][0];
#pragma unroll
    for (int m = 0; m < 4; ++m) {
        int gi = arow0 + ty * 4 + m;
        float4 v = make_float4(s[m][0], s[m][1], s[m][2], s[m][3]);
        *(float4*)&dst[(size_t)gi * NDET + brow0 + tx * 4] = v;
    }
}

// ---------------- 3. combine halves (f64), threshold, pack bits, flags ------
// grid (NDET, 2), 128 threads; thread t handles j = 4t..4t+3 via float4 loads.
__global__ void epilogue_kernel() {
    int i = blockIdx.x;
    int side = blockIdx.y;
    int tid = threadIdx.x;
    __shared__ unsigned int words[16];
    if (tid < 16) words[tid] = 0;
    __syncthreads();

    double den = g_ud[side][i] + EPSV;
    int j0 = tid * 4;
    float4 a = *(const float4*)&g_partial[side][0][i][j0];
    float4 b = *(const float4*)&g_partial[side][1][i][j0];
    float pa[4] = {a.x, a.y, a.z, a.w};
    float pb[4] = {b.x, b.y, b.z, b.w};
    unsigned int nib = 0;
#pragma unroll
    for (int n = 0; n < 4; ++n) {
        double inter = (double)pa[n] + (double)pb[n];
        double mg = inter - 0.5 * den;
        if (mg >= 0.0) nib |= (1u << n);
        int gj = j0 + n;
        if (gj > i && fabs(mg) <= TAU * den) {
            int idx = atomicAdd(&g_nflag, 1);
            if (idx < FLAG_CAP)
                g_flags[idx] = (side << 20) | (i << 10) | gj;
        }
    }
    atomicOr(&words[tid >> 3], nib << ((tid & 7) * 4));
    __syncthreads();
    if (tid < 16) g_bits[side][i][tid] = words[tid];
}

// ---------------- 4. exact f64 refinement of near-threshold pairs -----------
__global__ void refine_kernel() {
    int lane = threadIdx.x & 31;
    int warp = (blockIdx.x * blockDim.x + threadIdx.x) >> 5;
    int nwarps = (gridDim.x * blockDim.x) >> 5;
    int n = g_nflag;
    if (n > FLAG_CAP) n = FLAG_CAP;
    for (int p = warp; p < n; p += nwarps) {
        int v = g_flags[p];
        int side = v >> 20, i = (v >> 10) & 1023, j = v & 1023;
        const float* Pi = g_Pf[side][i];
        const float* Pj = g_Pf[side][j];
        double sum = 0.0;
#pragma unroll
        for (int q = 0; q < 25; ++q) {
            int k = lane + q * 32;
            float a = (k < HW) ? Pi[k] : 0.0f;
            float b = (k < HW) ? Pj[k] : 0.0f;
            sum = fma((double)a, (double)b, sum);
        }
        for (int o = 16; o; o >>= 1) sum += __shfl_down_sync(0xffffffffu, sum, o);
        if (lane == 0) {
            double den = g_ud[side][i] + EPSV;
            unsigned int bit = 1u << (j & 31);
            unsigned int* w = &g_bits[side][i][j >> 5];
            if (sum / den >= NMS_THRESH) atomicOr(w, bit);
            else                         atomicAnd(w, ~bit);
        }
    }
}

// ---------------- 5. skip-NMS (warps 0/1) + finalize, one block -------------
__global__ void nmsfin_kernel(float* __restrict__ out, int out_size) {
    int tid = threadIdx.x;
    int lane = tid & 31;
    int warp = tid >> 5;
    __shared__ unsigned int s_sup[2][16];

    if (warp < 2) {
        int side = warp;
        unsigned int removed = 0;   // lane w<16 holds suppression word w
        int i = 0;                  // top-ranked row always kept
        while (true) {
            int rw = i >> 5, rbit = i & 31;
            unsigned int hi = (rbit == 31) ? 0u : (0xFFFFFFFFu << (rbit + 1));
            unsigned int m = (lane < 16) ? g_bits[side][i][lane] : 0u;
            if (lane < rw) m = 0u;
            else if (lane == rw) m &= hi;
            removed |= m;
            unsigned int cand = (lane < 16) ? ~removed : 0u;
            if (lane < rw) cand = 0u;
            else if (lane == rw) cand &= hi;
            unsigned int ball = __ballot_sync(0xffffffffu, cand != 0u);
            if (!ball) break;
            int w = __ffs(ball) - 1;
            unsigned int word = __shfl_sync(0xffffffffu, cand, w);
            i = w * 32 + __ffs(word) - 1;
        }
        if (lane < 16) s_sup[side][lane] = removed;
    }
    __syncthreads();

    int r = tid;
    int n = g_order[r];
    bool valid = (g_ud[0][r] > 0.0) && (g_ud[1][r] > 0.0);
    bool supL = (s_sup[0][r >> 5] >> (r & 31)) & 1u;
    bool supR = (s_sup[1][r >> 5] >> (r & 31)) & 1u;
    float k = (valid && !supL && !supR) ? 1.0f : 0.0f;
    if (out_size >= 2 * NDET * HW + NDET)
        out[2 * NDET * HW + n] = k;
}

// ---------------- launch -----------------------------------------------------
extern "C" void kernel_launch(void* const* d_in, const int* in_sizes, int n_in,
                              void* d_out, int out_size) {
    const float* left   = (const float*)d_in[0];
    const float* right  = (const float*)d_in[1];
    const float* scores = (const float*)d_in[2];
    const int*   labels = (const int*)d_in[3];
    float* out = (float*)d_out;
    (void)in_sizes; (void)n_in;

    prob_kernel<<<2 * NDET, 256>>>(left, right, scores, labels, out);
    dim3 ggrid(8, 8, 4);
    gemm_partial_kernel<<<ggrid, 256>>>();
    dim3 egrid(NDET, 2);
    epilogue_kernel<<<egrid, 128>>>();
    refine_kernel<<<16, 256>>>();
    nmsfin_kernel<<<1, NDET>>>(out, out_size);
}